// round 16
// baseline (speedup 1.0000x reference)
#include <cuda_runtime.h>
#include <cuda_bf16.h>
#include <cstddef>
#include <cstdint>

#define T_   512
#define B_   64
#define H_   512
#define G3   1536   // 3*H
#define NCTA 128

// ---------------- device scratch ----------------
__device__ float g_h0[B_ * H_];
__device__ float g_h1[B_ * H_];
__device__ float g_gh0[B_ * G3];
__device__ float g_gh1[B_ * G3];
__device__ float g_gi0[2][B_ * G3];            // parity-buffered (role3 runs ahead)
__device__ float g_gi1[2][B_ * G3];            // parity-buffered
__device__ float g_dummy[B_ * H_];
__device__ unsigned g_cg[NCTA * 32];           // per-CTA GEMM-done counter (128B apart)
__device__ unsigned g_cp[NCTA * 32];           // per-CTA phase2-done counter

// packed bf16 hi/lo planes: one uint2 {hi(bf16x2), lo(bf16x2)} per 2 columns
__device__ uint2 g_h0p[B_ * 256];
__device__ uint2 g_h1p[B_ * 256];
__device__ uint2 g_y0p[(size_t)T_ * B_ * 256]; // layer-0 output, packed
__device__ uint2 g_xp [(size_t)T_ * B_ * 256]; // input x, packed (prologue)

// ---------------- mma / ldmatrix wrappers ----------------
__device__ __forceinline__ void mma_bf16(float* d, const uint32_t* a, const uint32_t* b) {
    asm volatile(
        "mma.sync.aligned.m16n8k16.row.col.f32.bf16.bf16.f32 "
        "{%0,%1,%2,%3}, {%4,%5,%6,%7}, {%8,%9}, {%0,%1,%2,%3};"
        : "+f"(d[0]), "+f"(d[1]), "+f"(d[2]), "+f"(d[3])
        : "r"(a[0]), "r"(a[1]), "r"(a[2]), "r"(a[3]), "r"(b[0]), "r"(b[1]));
}
__device__ __forceinline__ void ldsm_x4(uint32_t* r, uint32_t addr) {
    asm volatile("ldmatrix.sync.aligned.m8n8.x4.shared.b16 {%0,%1,%2,%3}, [%4];"
                 : "=r"(r[0]), "=r"(r[1]), "=r"(r[2]), "=r"(r[3]) : "r"(addr));
}
__device__ __forceinline__ void ldsm_x2(uint32_t* r, uint32_t addr) {
    asm volatile("ldmatrix.sync.aligned.m8n8.x2.shared.b16 {%0,%1}, [%2];"
                 : "=r"(r[0]), "=r"(r[1]) : "r"(addr));
}
// pack two f32 -> bf16x2 {lo=x, hi=y}
__device__ __forceinline__ uint32_t pack_bf16(float x, float y) {
    uint32_t p;
    asm("cvt.rn.bf16x2.f32 %0, %1, %2;" : "=r"(p) : "f"(y), "f"(x));
    return p;
}
__device__ __forceinline__ float bf_lo(uint32_t p) { return __uint_as_float(p << 16); }
__device__ __forceinline__ float bf_hi(uint32_t p) { return __uint_as_float(p & 0xffff0000u); }

// smem swizzle: row stride 1024B (512 bf16), XOR 16B-chunk index with row%8
__device__ __forceinline__ uint32_t swz(uint32_t row, uint32_t kbyte) {
    return (((row << 10) + kbyte) ^ ((row & 7u) << 4));
}

// smem plane byte offsets
#define SM_AHI 0
#define SM_ALO 65536
#define SM_BHI 131072
#define SM_BLO 180224
#define SM_FUSED 229376

// ---------------- group semaphores (release/acquire, tid0-only release) ------
__device__ __forceinline__ void waitset(const unsigned* ctr, int b0, int b1, int tgt) {
    if (tgt <= 0) return;
    if (threadIdx.x < 32) {
        const unsigned* p0 = &ctr[(b0 + (int)threadIdx.x) * 32];
        const unsigned* p1 = &ctr[(b1 + (int)threadIdx.x) * 32];
        unsigned c;
        do {
            asm volatile("ld.acquire.gpu.global.u32 %0, [%1];"
                         : "=r"(c) : "l"(p0) : "memory");
            if (c < (unsigned)tgt) __nanosleep(20);
        } while (c < (unsigned)tgt);
        do {
            asm volatile("ld.acquire.gpu.global.u32 %0, [%1];"
                         : "=r"(c) : "l"(p1) : "memory");
            if (c < (unsigned)tgt) __nanosleep(20);
        } while (c < (unsigned)tgt);
    }
    __syncthreads();   // broadcast acquired view CTA-wide
}

__device__ __forceinline__ void signal(unsigned* ctr, unsigned v) {
    __syncthreads();   // cumulative CTA fence collects all threads' writes
    if (threadIdx.x == 0)
        asm volatile("st.release.gpu.global.u32 [%0], %1;"
                     :: "l"(&ctr[blockIdx.x * 32]), "r"(v) : "memory");
}

// ---------------- fused block reductions (256 threads) ----------------
__device__ __forceinline__ void blockReduce4(float& a, float& b, float& c, float& d,
                                             float* red) {
    int tid = threadIdx.x, lane = tid & 31, wid = tid >> 5;
#pragma unroll
    for (int o = 16; o; o >>= 1) {
        a += __shfl_xor_sync(0xffffffffu, a, o);
        b += __shfl_xor_sync(0xffffffffu, b, o);
        c += __shfl_xor_sync(0xffffffffu, c, o);
        d += __shfl_xor_sync(0xffffffffu, d, o);
    }
    if (lane == 0) { red[wid] = a; red[8 + wid] = b; red[16 + wid] = c; red[24 + wid] = d; }
    __syncthreads();
    if (tid < 32) {
        int g = lane >> 3, k = lane & 7;
        float v = red[g * 8 + k];
#pragma unroll
        for (int o = 4; o; o >>= 1) v += __shfl_xor_sync(0xffffffffu, v, o);
        if (k == 0) red[32 + g] = v;
    }
    __syncthreads();
    a = red[32]; b = red[33]; c = red[34]; d = red[35];
}

__device__ __forceinline__ void blockReduce2s(float& a, float& b, float* red) {
    int tid = threadIdx.x, lane = tid & 31, wid = tid >> 5;
#pragma unroll
    for (int o = 16; o; o >>= 1) {
        a += __shfl_xor_sync(0xffffffffu, a, o);
        b += __shfl_xor_sync(0xffffffffu, b, o);
    }
    __syncthreads();
    if (lane == 0) { red[wid] = a; red[8 + wid] = b; }
    __syncthreads();
    if (tid < 32) {
        int g = lane >> 3, k = lane & 7;
        float v = (g < 2) ? red[g * 8 + k] : 0.0f;
#pragma unroll
        for (int o = 4; o; o >>= 1) v += __shfl_xor_sync(0xffffffffu, v, o);
        if (k == 0 && g < 2) red[40 + g] = v;
    }
    __syncthreads();
    a = red[40]; b = red[41];
}

// ---------------- prologue: pack x into bf16 hi/lo planes ----------------
__global__ void k_packx(const float* __restrict__ x) {
    size_t e = (size_t)blockIdx.x * blockDim.x + threadIdx.x;  // 8,388,608 entries
    float2 a = *reinterpret_cast<const float2*>(x + 2 * e);
    uint32_t hi = pack_bf16(a.x, a.y);
    uint32_t lo = pack_bf16(a.x - bf_lo(hi), a.y - bf_hi(hi));
    g_xp[e] = make_uint2(hi, lo);
}

// ---------------- init: h states (fp32 + packed) and counters ----------------
__global__ void k_init(const float* __restrict__ h0) {
    int i = blockIdx.x * blockDim.x + threadIdx.x;   // 32768
    g_h0[i] = h0[i];
    g_h1[i] = h0[B_ * H_ + i];
    if (i < NCTA * 32) { g_cg[i] = 0u; g_cp[i] = 0u; }
    if (i < B_ * H_ / 2) {
        float2 a = *reinterpret_cast<const float2*>(h0 + 2 * i);
        uint32_t hi = pack_bf16(a.x, a.y);
        uint32_t lo = pack_bf16(a.x - bf_lo(hi), a.y - bf_hi(hi));
        g_h0p[i] = make_uint2(hi, lo);
        float2 b = *reinterpret_cast<const float2*>(h0 + B_ * H_ + 2 * i);
        uint32_t hib = pack_bf16(b.x, b.y);
        uint32_t lob = pack_bf16(b.x - bf_lo(hib), b.y - bf_hi(hib));
        g_h1p[i] = make_uint2(hib, lob);
    }
}

// ---------------- fused 2-layer pipelined recurrence, semaphore-synced -------
// Roles: bx>>5 -> 0: gh0, 1: gh1, 2: gi1, 3: gi0. Phase-2 ownership follows
// the producer chains: L0 on CTAs {0-31, 96-127}; L1 on CTAs {32-95}.
__global__ void __launch_bounds__(256, 1) k_fused(
    const float* __restrict__ Whh0, const float* __restrict__ Whh1,
    const float* __restrict__ Wih0, const float* __restrict__ Wih1,
    const float* __restrict__ bih,  const float* __restrict__ bhh,
    const float* __restrict__ lng,  const float* __restrict__ lnb,
    float* __restrict__ out, float* __restrict__ hl0, float* __restrict__ hl1)
{
    extern __shared__ char smem_raw[];
    float* red = reinterpret_cast<float*>(smem_raw);   // phase-2 reduction scratch

    uint32_t sbase;
    asm("{.reg .u64 t; cvta.to.shared.u64 t, %1; cvt.u32.u64 %0, t;}"
        : "=r"(sbase) : "l"(smem_raw));

    const int tid  = threadIdx.x;
    const int bx   = blockIdx.x;
    const int role = bx >> 5;          // 0: gh0, 1: gh1, 2: gi1, 3: gi0
    const int tile = bx & 31;
    const int n0   = tile * 48;

    // ---- stage + convert weight tile once: 48 x 512 fp32 -> bf16 hi/lo ----
    {
        const float* Wp = (role == 0) ? Whh0 : (role == 1) ? Whh1
                        : (role == 2) ? Wih1 : Wih0;
        Wp += (size_t)n0 * 512;
#pragma unroll
        for (int r = 0; r < 24; r++) {
            int idx = tid + r * 256;             // 48*128 float4 units
            int row = idx >> 7, k = (idx & 127) * 4;
            float4 v = *reinterpret_cast<const float4*>(&Wp[(size_t)row * 512 + k]);
            uint32_t p0 = pack_bf16(v.x, v.y), p1 = pack_bf16(v.z, v.w);
            uint32_t q0 = pack_bf16(v.x - bf_lo(p0), v.y - bf_hi(p0));
            uint32_t q1 = pack_bf16(v.z - bf_lo(p1), v.w - bf_hi(p1));
            uint32_t off = swz((uint32_t)row, (uint32_t)k * 2);
            *reinterpret_cast<uint2*>(smem_raw + SM_BHI + off) = make_uint2(p0, p1);
            *reinterpret_cast<uint2*>(smem_raw + SM_BLO + off) = make_uint2(q0, q1);
        }
    }

    // ---- per-warp fragment address precompute ----
    const int lane = tid & 31;
    const int warp = tid >> 5;
    const int mb   = (warp & 3) * 16;        // m16 tile base (b rows)
    const int nw   = (warp >> 2) * 24;       // n24 warp base (tile-local)

    const uint32_t aRow  = (uint32_t)(mb + (lane & 15));
    const uint32_t aPre  = (aRow << 10) + (uint32_t)((lane >> 4) * 16);
    const uint32_t aXor  = (aRow & 7u) << 4;
    const uint32_t b4Row = (uint32_t)(nw + ((lane >> 4) << 3) + (lane & 7));
    const uint32_t b4Pre = (b4Row << 10) + (uint32_t)(((lane >> 3) & 1) * 16);
    const uint32_t b4Xor = (b4Row & 7u) << 4;
    const int l2 = lane & 15;
    const uint32_t b2Row = (uint32_t)(nw + 16 + (l2 & 7));
    const uint32_t b2Pre = (b2Row << 10) + (uint32_t)((l2 >> 3) * 16);
    const uint32_t b2Xor = (b2Row & 7u) << 4;

    // phase-2 ownership: chain-local
    int layer, b2i;
    if (bx < 32)      { layer = 0; b2i = bx; }
    else if (bx < 96) { layer = 1; b2i = bx - 32; }
    else              { layer = 0; b2i = bx - 64; }

    for (int s = 0; s <= T_; s++) {
        const int par = s & 1;
        // ================= GEMM phase (narrow producer waits) =================
        bool gemm_on = (role == 0 || role == 3) ? (s < T_) : (s >= 1);
        if (gemm_on) {
            // true-dependence / WAR waits (targets derived per edge):
            if (role == 0)      waitset(g_cp, 0, 96, s);          // h0 after P2L0(s-1)
            else if (role == 1) waitset(g_cp, 32, 64, s);         // h1 after P2L1(s-1)
            else if (role == 2) { waitset(g_cp, 0, 96, s);        // y0[s-1] from P2L0(s-1)
                                  waitset(g_cp, 32, 64, s - 1); } // gi1 parity WAR
            else                 waitset(g_cp, 0, 96, s - 1);     // gi0 parity WAR

            const uint2* inp = (role == 0) ? g_h0p
                             : (role == 1) ? g_h1p
                             : (role == 2) ? (g_y0p + (size_t)(s - 1) * B_ * 256)
                                           : (g_xp + (size_t)s * B_ * 256);
            // stage pre-packed tile: pure copy, no conversion
#pragma unroll
            for (int r = 0; r < 32; r++) {
                int idx = tid + r * 256;          // 64 rows * 128 uint4 units
                int row = idx >> 7, c = idx & 127;
                uint4 v = __ldcg(reinterpret_cast<const uint4*>(inp + (size_t)row * 256) + c);
                uint32_t off = swz((uint32_t)row, (uint32_t)c * 8);
                *reinterpret_cast<uint2*>(smem_raw + SM_AHI + off) = make_uint2(v.x, v.z);
                *reinterpret_cast<uint2*>(smem_raw + SM_ALO + off) = make_uint2(v.y, v.w);
            }
            __syncthreads();

            float accH[3][4], accX[3][4];
#pragma unroll
            for (int n = 0; n < 3; n++)
#pragma unroll
                for (int i = 0; i < 4; i++) { accH[n][i] = 0.f; accX[n][i] = 0.f; }

#pragma unroll 4
            for (uint32_t kb = 0; kb < 1024; kb += 32) {
                uint32_t ah[4], al[4], bh01[4], bl01[4], bh2[2], bl2[2];
                uint32_t aoff  = ((aPre + kb) ^ aXor);
                uint32_t b4off = ((b4Pre + kb) ^ b4Xor);
                uint32_t b2off = ((b2Pre + kb) ^ b2Xor);
                ldsm_x4(ah,   sbase + SM_AHI + aoff);
                ldsm_x4(al,   sbase + SM_ALO + aoff);
                ldsm_x4(bh01, sbase + SM_BHI + b4off);
                ldsm_x4(bl01, sbase + SM_BLO + b4off);
                ldsm_x2(bh2,  sbase + SM_BHI + b2off);
                ldsm_x2(bl2,  sbase + SM_BLO + b2off);

                mma_bf16(accH[0], ah, bh01 + 0);
                mma_bf16(accH[1], ah, bh01 + 2);
                mma_bf16(accH[2], ah, bh2);
                mma_bf16(accX[0], ah, bl01 + 0);
                mma_bf16(accX[1], ah, bl01 + 2);
                mma_bf16(accX[2], ah, bl2);
                mma_bf16(accX[0], al, bh01 + 0);
                mma_bf16(accX[1], al, bh01 + 2);
                mma_bf16(accX[2], al, bh2);
            }

            float* gout = (role == 0) ? g_gh0 : (role == 1) ? g_gh1
                        : (role == 2) ? g_gi1[par] : g_gi0[par];
            const int r0 = mb + (lane >> 2);
            const int c0 = n0 + nw + 2 * (lane & 3);
#pragma unroll
            for (int n = 0; n < 3; n++) {
                int c = c0 + 8 * n;
                float2 v0 = make_float2(accH[n][0] + accX[n][0],
                                        accH[n][1] + accX[n][1]);
                float2 v1 = make_float2(accH[n][2] + accX[n][2],
                                        accH[n][3] + accX[n][3]);
                *reinterpret_cast<float2*>(&gout[(size_t)r0 * G3 + c])       = v0;
                *reinterpret_cast<float2*>(&gout[(size_t)(r0 + 8) * G3 + c]) = v1;
            }

            // role 3: warm L2 with next step's packed x tile (off critical path)
            if (role == 3 && s + 1 < T_) {
                const char* xn = (const char*)(g_xp + (size_t)(s + 1) * B_ * 256);
#pragma unroll
                for (int q = 0; q < 4; q++) {
                    const char* p = xn + (size_t)(tid + q * 256) * 128;
                    asm volatile("prefetch.global.L2 [%0];" :: "l"(p));
                }
            }
        }

        signal(g_cg, (unsigned)(s + 1));

        // ================= phase 2 (waits only on its producer roles) ==========
        bool p2_on = (layer == 0) ? (s < T_) : (s >= 1);
        if (p2_on) {
            if (layer == 0) waitset(g_cg, 0, 96, s + 1);
            else            waitset(g_cg, 32, 64, s + 1);

            const int t = (layer == 0) ? s : (s - 1);
            const float* gh = (layer ? g_gh1 : g_gh0) + (size_t)b2i * G3;
            const float* gi = (layer ? g_gi1[par] : g_gi0[par]) + (size_t)b2i * G3;
            const float* bi = bih + layer * G3;
            const float* bh = bhh + layer * G3;
            const float* lg = lng + layer * G3;
            const float* lb = lnb + layer * G3;

            const int j0 = 2 * tid;   // two consecutive columns per thread

            float2 ghr = __ldcg(reinterpret_cast<const float2*>(&gh[j0]));
            float2 ghi = __ldcg(reinterpret_cast<const float2*>(&gh[512 + j0]));
            float2 ghn = __ldcg(reinterpret_cast<const float2*>(&gh[1024 + j0]));
            float2 gir = __ldcg(reinterpret_cast<const float2*>(&gi[j0]));
            float2 gii = __ldcg(reinterpret_cast<const float2*>(&gi[512 + j0]));
            float2 gin = __ldcg(reinterpret_cast<const float2*>(&gi[1024 + j0]));
            float2 bir = *reinterpret_cast<const float2*>(&bi[j0]);
            float2 bii = *reinterpret_cast<const float2*>(&bi[512 + j0]);
            float2 bin = *reinterpret_cast<const float2*>(&bi[1024 + j0]);
            float2 bhr = *reinterpret_cast<const float2*>(&bh[j0]);
            float2 bhi = *reinterpret_cast<const float2*>(&bh[512 + j0]);
            float2 bhn = *reinterpret_cast<const float2*>(&bh[1024 + j0]);

            float2 A  = make_float2(gir.x + bir.x + ghr.x + bhr.x,
                                    gir.y + bir.y + ghr.y + bhr.y);
            float2 Bv = make_float2(gii.x + bii.x + ghi.x + bhi.x,
                                    gii.y + bii.y + ghi.y + bhi.y);
            float2 Ch = make_float2(ghn.x + bhn.x, ghn.y + bhn.y);
            float2 Dn = make_float2(gin.x + bin.x, gin.y + bin.y);

            float sr = A.x + A.y,   qr = A.x * A.x + A.y * A.y;
            float si = Bv.x + Bv.y, qi = Bv.x * Bv.x + Bv.y * Bv.y;
            blockReduce4(sr, qr, si, qi, red);

            const float inv = 1.0f / 512.0f;
            float mur = sr * inv, rr = rsqrtf(qr * inv - mur * mur + 1e-5f);
            float mui = si * inv, ri = rsqrtf(qi * inv - mui * mui + 1e-5f);

            float2 lgr = *reinterpret_cast<const float2*>(&lg[j0]);
            float2 lbr = *reinterpret_cast<const float2*>(&lb[j0]);
            float2 lgi = *reinterpret_cast<const float2*>(&lg[512 + j0]);
            float2 lbi = *reinterpret_cast<const float2*>(&lb[512 + j0]);

            float rgx = 1.0f / (1.0f + __expf(-((A.x - mur) * rr * lgr.x + lbr.x)));
            float rgy = 1.0f / (1.0f + __expf(-((A.y - mur) * rr * lgr.y + lbr.y)));
            float igx = 1.0f / (1.0f + __expf(-((Bv.x - mui) * ri * lgi.x + lbi.x)));
            float igy = 1.0f / (1.0f + __expf(-((Bv.y - mui) * ri * lgi.y + lbi.y)));

            float2 Cn = make_float2(Dn.x + rgx * Ch.x, Dn.y + rgy * Ch.y);

            float sn = Cn.x + Cn.y, qn = Cn.x * Cn.x + Cn.y * Cn.y;
            blockReduce2s(sn, qn, red);
            float mun = sn * inv, rn = rsqrtf(qn * inv - mun * mun + 1e-5f);

            float2 lgn = *reinterpret_cast<const float2*>(&lg[1024 + j0]);
            float2 lbn = *reinterpret_cast<const float2*>(&lb[1024 + j0]);

            float ngx = tanhf((Cn.x - mun) * rn * lgn.x + lbn.x);
            float ngy = tanhf((Cn.y - mun) * rn * lgn.y + lbn.y);

            float* hcur = layer ? g_h1 : g_h0;
            float2 hold = *reinterpret_cast<const float2*>(&hcur[b2i * 512 + j0]);
            float2 hy = make_float2(ngx + igx * (hold.x - ngx),
                                    ngy + igy * (hold.y - ngy));
            *reinterpret_cast<float2*>(&hcur[b2i * 512 + j0]) = hy;

            // packed hi/lo emission (same decomposition the stagers used before)
            uint32_t phi = pack_bf16(hy.x, hy.y);
            uint32_t plo = pack_bf16(hy.x - bf_lo(phi), hy.y - bf_hi(phi));
            uint2 pk = make_uint2(phi, plo);
            if (layer == 0) {
                g_h0p[b2i * 256 + tid] = pk;
                g_y0p[((size_t)t * B_ + b2i) * 256 + tid] = pk;
                if (t == T_ - 1)
                    *reinterpret_cast<float2*>(&hl0[b2i * 512 + j0]) = hy;
            } else {
                g_h1p[b2i * 256 + tid] = pk;
                *reinterpret_cast<float2*>(&out[((size_t)t * B_ + b2i) * H_ + j0]) = hy;
                if (t == T_ - 1)
                    *reinterpret_cast<float2*>(&hl1[b2i * 512 + j0]) = hy;
            }
        }

        signal(g_cp, (unsigned)(s + 1));
    }
}

// ---------------- launcher ----------------
extern "C" void kernel_launch(void* const* d_in, const int* in_sizes, int n_in,
                              void* d_out, int out_size) {
    (void)in_sizes; (void)n_in;
    const float* x   = (const float*)d_in[0];
    const float* h0  = (const float*)d_in[1];
    const float* Wih = (const float*)d_in[2];
    const float* bih = (const float*)d_in[3];
    const float* Whh = (const float*)d_in[4];
    const float* bhh = (const float*)d_in[5];
    const float* lng = (const float*)d_in[6];
    const float* lnb = (const float*)d_in[7];
    float* out = (float*)d_out;

    const size_t TBH = (size_t)T_ * B_ * H_;
    const size_t LBH = (size_t)2 * B_ * H_;
    bool has_hl = ((size_t)out_size >= TBH + LBH);

    float* hl_dummy = nullptr;
    cudaGetSymbolAddress((void**)&hl_dummy, g_dummy);
    float* hl0 = has_hl ? out + TBH           : hl_dummy;
    float* hl1 = has_hl ? out + TBH + B_ * H_ : hl_dummy;

    cudaFuncSetAttribute(k_fused, cudaFuncAttributeMaxDynamicSharedMemorySize,
                         SM_FUSED);

    // prologue: pack x (T*B*H/2 = 8,388,608 uint2 entries)
    k_packx<<<32768, 256>>>(x);
    k_init<<<NCTA, 256>>>(h0);
    k_fused<<<NCTA, 256, SM_FUSED>>>(
        Whh, Whh + (size_t)G3 * H_,
        Wih, Wih + (size_t)G3 * H_,
        bih, bhh, lng, lnb, out, hl0, hl1);
}

// round 17
// speedup vs baseline: 1.0427x; 1.0427x over previous
#include <cuda_runtime.h>
#include <cuda_bf16.h>
#include <cstddef>
#include <cstdint>

#define T_   512
#define B_   64
#define H_   512
#define G3   1536   // 3*H
#define NCTA 128

// ---------------- device scratch ----------------
__device__ float g_h0[B_ * H_];
__device__ float g_h1[B_ * H_];
__device__ float g_gh0[B_ * G3];
__device__ float g_gh1[B_ * G3];
__device__ float g_gi0[2][B_ * G3];            // parity-buffered (role3 runs ahead)
__device__ float g_gi1[2][B_ * G3];            // parity-buffered
__device__ float g_dummy[B_ * H_];
__device__ unsigned g_cg[NCTA * 32];           // per-CTA GEMM-done counter (128B apart)
__device__ unsigned g_cp[NCTA * 32];           // per-CTA phase2-done counter

// packed bf16 hi/lo planes: one uint2 {hi(bf16x2), lo(bf16x2)} per 2 columns
__device__ uint2 g_h0p[B_ * 256];
__device__ uint2 g_h1p[B_ * 256];
__device__ uint2 g_y0p[(size_t)T_ * B_ * 256]; // layer-0 output, packed
__device__ uint2 g_xp [(size_t)T_ * B_ * 256]; // input x, packed (prologue)

// ---------------- mma / ldmatrix wrappers ----------------
__device__ __forceinline__ void mma_bf16(float* d, const uint32_t* a, const uint32_t* b) {
    asm volatile(
        "mma.sync.aligned.m16n8k16.row.col.f32.bf16.bf16.f32 "
        "{%0,%1,%2,%3}, {%4,%5,%6,%7}, {%8,%9}, {%0,%1,%2,%3};"
        : "+f"(d[0]), "+f"(d[1]), "+f"(d[2]), "+f"(d[3])
        : "r"(a[0]), "r"(a[1]), "r"(a[2]), "r"(a[3]), "r"(b[0]), "r"(b[1]));
}
__device__ __forceinline__ void ldsm_x4(uint32_t* r, uint32_t addr) {
    asm volatile("ldmatrix.sync.aligned.m8n8.x4.shared.b16 {%0,%1,%2,%3}, [%4];"
                 : "=r"(r[0]), "=r"(r[1]), "=r"(r[2]), "=r"(r[3]) : "r"(addr));
}
__device__ __forceinline__ void ldsm_x2(uint32_t* r, uint32_t addr) {
    asm volatile("ldmatrix.sync.aligned.m8n8.x2.shared.b16 {%0,%1}, [%2];"
                 : "=r"(r[0]), "=r"(r[1]) : "r"(addr));
}
// pack two f32 -> bf16x2 {lo=x, hi=y}
__device__ __forceinline__ uint32_t pack_bf16(float x, float y) {
    uint32_t p;
    asm("cvt.rn.bf16x2.f32 %0, %1, %2;" : "=r"(p) : "f"(y), "f"(x));
    return p;
}
__device__ __forceinline__ float bf_lo(uint32_t p) { return __uint_as_float(p << 16); }
__device__ __forceinline__ float bf_hi(uint32_t p) { return __uint_as_float(p & 0xffff0000u); }

// smem swizzle: row stride 1024B (512 bf16), XOR 16B-chunk index with row%8
__device__ __forceinline__ uint32_t swz(uint32_t row, uint32_t kbyte) {
    return (((row << 10) + kbyte) ^ ((row & 7u) << 4));
}

// smem plane byte offsets
#define SM_AHI 0
#define SM_ALO 65536
#define SM_BHI 131072
#define SM_BLO 180224
#define SM_FUSED 229376

// ---------------- group semaphores (release/acquire, tid0-only release) ------
// Wait until counters of CTA ranges [b0,b0+32) and [b1,b1+32) reach tgt.
// 64 pollers, ONE counter each: detection = one L2 round trip after release.
__device__ __forceinline__ void waitset(const unsigned* ctr, int b0, int b1, int tgt) {
    if (tgt <= 0) return;
    const int t = threadIdx.x;
    if (t < 64) {
        const int idx = (t < 32) ? (b0 + t) : (b1 + (t - 32));
        const unsigned* p = &ctr[idx * 32];
        unsigned c;
        asm volatile("ld.acquire.gpu.global.u32 %0, [%1];"
                     : "=r"(c) : "l"(p) : "memory");
        while (c < (unsigned)tgt) {
            __nanosleep(32);
            asm volatile("ld.acquire.gpu.global.u32 %0, [%1];"
                         : "=r"(c) : "l"(p) : "memory");
        }
    }
    __syncthreads();   // broadcast acquired view CTA-wide
}

__device__ __forceinline__ void signal(unsigned* ctr, unsigned v) {
    __syncthreads();   // cumulative CTA fence collects all threads' writes
    if (threadIdx.x == 0)
        asm volatile("st.release.gpu.global.u32 [%0], %1;"
                     :: "l"(&ctr[blockIdx.x * 32]), "r"(v) : "memory");
}

// ---------------- fused block reductions (256 threads) ----------------
__device__ __forceinline__ void blockReduce4(float& a, float& b, float& c, float& d,
                                             float* red) {
    int tid = threadIdx.x, lane = tid & 31, wid = tid >> 5;
#pragma unroll
    for (int o = 16; o; o >>= 1) {
        a += __shfl_xor_sync(0xffffffffu, a, o);
        b += __shfl_xor_sync(0xffffffffu, b, o);
        c += __shfl_xor_sync(0xffffffffu, c, o);
        d += __shfl_xor_sync(0xffffffffu, d, o);
    }
    if (lane == 0) { red[wid] = a; red[8 + wid] = b; red[16 + wid] = c; red[24 + wid] = d; }
    __syncthreads();
    if (tid < 32) {
        int g = lane >> 3, k = lane & 7;
        float v = red[g * 8 + k];
#pragma unroll
        for (int o = 4; o; o >>= 1) v += __shfl_xor_sync(0xffffffffu, v, o);
        if (k == 0) red[32 + g] = v;
    }
    __syncthreads();
    a = red[32]; b = red[33]; c = red[34]; d = red[35];
}

__device__ __forceinline__ void blockReduce2s(float& a, float& b, float* red) {
    int tid = threadIdx.x, lane = tid & 31, wid = tid >> 5;
#pragma unroll
    for (int o = 16; o; o >>= 1) {
        a += __shfl_xor_sync(0xffffffffu, a, o);
        b += __shfl_xor_sync(0xffffffffu, b, o);
    }
    __syncthreads();
    if (lane == 0) { red[wid] = a; red[8 + wid] = b; }
    __syncthreads();
    if (tid < 32) {
        int g = lane >> 3, k = lane & 7;
        float v = (g < 2) ? red[g * 8 + k] : 0.0f;
#pragma unroll
        for (int o = 4; o; o >>= 1) v += __shfl_xor_sync(0xffffffffu, v, o);
        if (k == 0 && g < 2) red[40 + g] = v;
    }
    __syncthreads();
    a = red[40]; b = red[41];
}

// ---------------- prologue: pack x into bf16 hi/lo planes ----------------
__global__ void k_packx(const float* __restrict__ x) {
    size_t e = (size_t)blockIdx.x * blockDim.x + threadIdx.x;  // 8,388,608 entries
    float2 a = *reinterpret_cast<const float2*>(x + 2 * e);
    uint32_t hi = pack_bf16(a.x, a.y);
    uint32_t lo = pack_bf16(a.x - bf_lo(hi), a.y - bf_hi(hi));
    g_xp[e] = make_uint2(hi, lo);
}

// ---------------- init: h states (fp32 + packed) and counters ----------------
__global__ void k_init(const float* __restrict__ h0) {
    int i = blockIdx.x * blockDim.x + threadIdx.x;   // 32768
    g_h0[i] = h0[i];
    g_h1[i] = h0[B_ * H_ + i];
    if (i < NCTA * 32) { g_cg[i] = 0u; g_cp[i] = 0u; }
    if (i < B_ * H_ / 2) {
        float2 a = *reinterpret_cast<const float2*>(h0 + 2 * i);
        uint32_t hi = pack_bf16(a.x, a.y);
        uint32_t lo = pack_bf16(a.x - bf_lo(hi), a.y - bf_hi(hi));
        g_h0p[i] = make_uint2(hi, lo);
        float2 b = *reinterpret_cast<const float2*>(h0 + B_ * H_ + 2 * i);
        uint32_t hib = pack_bf16(b.x, b.y);
        uint32_t lob = pack_bf16(b.x - bf_lo(hib), b.y - bf_hi(hib));
        g_h1p[i] = make_uint2(hib, lob);
    }
}

// ---------------- fused 2-layer pipelined recurrence, semaphore-synced -------
// Roles: bx>>5 -> 0: gh0, 1: gh1, 2: gi1, 3: gi0. Phase-2 ownership follows
// the producer chains: L0 on CTAs {0-31, 96-127}; L1 on CTAs {32-95}.
__global__ void __launch_bounds__(256, 1) k_fused(
    const float* __restrict__ Whh0, const float* __restrict__ Whh1,
    const float* __restrict__ Wih0, const float* __restrict__ Wih1,
    const float* __restrict__ bih,  const float* __restrict__ bhh,
    const float* __restrict__ lng,  const float* __restrict__ lnb,
    float* __restrict__ out, float* __restrict__ hl0, float* __restrict__ hl1)
{
    extern __shared__ char smem_raw[];
    float* red = reinterpret_cast<float*>(smem_raw);   // phase-2 reduction scratch

    uint32_t sbase;
    asm("{.reg .u64 t; cvta.to.shared.u64 t, %1; cvt.u32.u64 %0, t;}"
        : "=r"(sbase) : "l"(smem_raw));

    const int tid  = threadIdx.x;
    const int bx   = blockIdx.x;
    const int role = bx >> 5;          // 0: gh0, 1: gh1, 2: gi1, 3: gi0
    const int tile = bx & 31;
    const int n0   = tile * 48;

    // ---- stage + convert weight tile once: 48 x 512 fp32 -> bf16 hi/lo ----
    {
        const float* Wp = (role == 0) ? Whh0 : (role == 1) ? Whh1
                        : (role == 2) ? Wih1 : Wih0;
        Wp += (size_t)n0 * 512;
#pragma unroll
        for (int r = 0; r < 24; r++) {
            int idx = tid + r * 256;             // 48*128 float4 units
            int row = idx >> 7, k = (idx & 127) * 4;
            float4 v = *reinterpret_cast<const float4*>(&Wp[(size_t)row * 512 + k]);
            uint32_t p0 = pack_bf16(v.x, v.y), p1 = pack_bf16(v.z, v.w);
            uint32_t q0 = pack_bf16(v.x - bf_lo(p0), v.y - bf_hi(p0));
            uint32_t q1 = pack_bf16(v.z - bf_lo(p1), v.w - bf_hi(p1));
            uint32_t off = swz((uint32_t)row, (uint32_t)k * 2);
            *reinterpret_cast<uint2*>(smem_raw + SM_BHI + off) = make_uint2(p0, p1);
            *reinterpret_cast<uint2*>(smem_raw + SM_BLO + off) = make_uint2(q0, q1);
        }
    }

    // ---- per-warp fragment address precompute ----
    const int lane = tid & 31;
    const int warp = tid >> 5;
    const int mb   = (warp & 3) * 16;        // m16 tile base (b rows)
    const int nw   = (warp >> 2) * 24;       // n24 warp base (tile-local)

    const uint32_t aRow  = (uint32_t)(mb + (lane & 15));
    const uint32_t aPre  = (aRow << 10) + (uint32_t)((lane >> 4) * 16);
    const uint32_t aXor  = (aRow & 7u) << 4;
    const uint32_t b4Row = (uint32_t)(nw + ((lane >> 4) << 3) + (lane & 7));
    const uint32_t b4Pre = (b4Row << 10) + (uint32_t)(((lane >> 3) & 1) * 16);
    const uint32_t b4Xor = (b4Row & 7u) << 4;
    const int l2 = lane & 15;
    const uint32_t b2Row = (uint32_t)(nw + 16 + (l2 & 7));
    const uint32_t b2Pre = (b2Row << 10) + (uint32_t)((l2 >> 3) * 16);
    const uint32_t b2Xor = (b2Row & 7u) << 4;

    // phase-2 ownership: chain-local
    int layer, b2i;
    if (bx < 32)      { layer = 0; b2i = bx; }
    else if (bx < 96) { layer = 1; b2i = bx - 32; }
    else              { layer = 0; b2i = bx - 64; }

    // phase-2 loop-invariant pointers
    const float* bi = bih + layer * G3;
    const float* bh = bhh + layer * G3;
    const float* lg = lng + layer * G3;
    const float* lb = lnb + layer * G3;
    const int j0 = 2 * tid;   // two consecutive columns per thread

    for (int s = 0; s <= T_; s++) {
        const int par = s & 1;
        // ================= GEMM phase (narrow producer waits) =================
        bool gemm_on = (role == 0 || role == 3) ? (s < T_) : (s >= 1);
        if (gemm_on) {
            // true-dependence / WAR waits (targets derived per edge):
            if (role == 0)      waitset(g_cp, 0, 96, s);          // h0 after P2L0(s-1)
            else if (role == 1) waitset(g_cp, 32, 64, s);         // h1 after P2L1(s-1)
            else if (role == 2) { waitset(g_cp, 0, 96, s);        // y0[s-1] from P2L0(s-1)
                                  waitset(g_cp, 32, 64, s - 1); } // gi1 parity WAR
            else                 waitset(g_cp, 0, 96, s - 1);     // gi0 parity WAR

            const uint2* inp = (role == 0) ? g_h0p
                             : (role == 1) ? g_h1p
                             : (role == 2) ? (g_y0p + (size_t)(s - 1) * B_ * 256)
                                           : (g_xp + (size_t)s * B_ * 256);
            // stage pre-packed tile: pure copy, no conversion
#pragma unroll
            for (int r = 0; r < 32; r++) {
                int idx = tid + r * 256;          // 64 rows * 128 uint4 units
                int row = idx >> 7, c = idx & 127;
                uint4 v = __ldcg(reinterpret_cast<const uint4*>(inp + (size_t)row * 256) + c);
                uint32_t off = swz((uint32_t)row, (uint32_t)c * 8);
                *reinterpret_cast<uint2*>(smem_raw + SM_AHI + off) = make_uint2(v.x, v.z);
                *reinterpret_cast<uint2*>(smem_raw + SM_ALO + off) = make_uint2(v.y, v.w);
            }
            __syncthreads();

            float accH[3][4], accX[3][4];
#pragma unroll
            for (int n = 0; n < 3; n++)
#pragma unroll
                for (int i = 0; i < 4; i++) { accH[n][i] = 0.f; accX[n][i] = 0.f; }

#pragma unroll 4
            for (uint32_t kb = 0; kb < 1024; kb += 32) {
                uint32_t ah[4], al[4], bh01[4], bl01[4], bh2[2], bl2[2];
                uint32_t aoff  = ((aPre + kb) ^ aXor);
                uint32_t b4off = ((b4Pre + kb) ^ b4Xor);
                uint32_t b2off = ((b2Pre + kb) ^ b2Xor);
                ldsm_x4(ah,   sbase + SM_AHI + aoff);
                ldsm_x4(al,   sbase + SM_ALO + aoff);
                ldsm_x4(bh01, sbase + SM_BHI + b4off);
                ldsm_x4(bl01, sbase + SM_BLO + b4off);
                ldsm_x2(bh2,  sbase + SM_BHI + b2off);
                ldsm_x2(bl2,  sbase + SM_BLO + b2off);

                mma_bf16(accH[0], ah, bh01 + 0);
                mma_bf16(accH[1], ah, bh01 + 2);
                mma_bf16(accH[2], ah, bh2);
                mma_bf16(accX[0], ah, bl01 + 0);
                mma_bf16(accX[1], ah, bl01 + 2);
                mma_bf16(accX[2], ah, bl2);
                mma_bf16(accX[0], al, bh01 + 0);
                mma_bf16(accX[1], al, bh01 + 2);
                mma_bf16(accX[2], al, bh2);
            }

            float* gout = (role == 0) ? g_gh0 : (role == 1) ? g_gh1
                        : (role == 2) ? g_gi1[par] : g_gi0[par];
            const int r0 = mb + (lane >> 2);
            const int c0 = n0 + nw + 2 * (lane & 3);
#pragma unroll
            for (int n = 0; n < 3; n++) {
                int c = c0 + 8 * n;
                float2 v0 = make_float2(accH[n][0] + accX[n][0],
                                        accH[n][1] + accX[n][1]);
                float2 v1 = make_float2(accH[n][2] + accX[n][2],
                                        accH[n][3] + accX[n][3]);
                *reinterpret_cast<float2*>(&gout[(size_t)r0 * G3 + c])       = v0;
                *reinterpret_cast<float2*>(&gout[(size_t)(r0 + 8) * G3 + c]) = v1;
            }

            // role 3: warm L2 with next step's packed x tile (off critical path)
            if (role == 3 && s + 1 < T_) {
                const char* xn = (const char*)(g_xp + (size_t)(s + 1) * B_ * 256);
#pragma unroll
                for (int q = 0; q < 4; q++) {
                    const char* p = xn + (size_t)(tid + q * 256) * 128;
                    asm volatile("prefetch.global.L2 [%0];" :: "l"(p));
                }
            }
        }

        signal(g_cg, (unsigned)(s + 1));

        // ================= phase 2 (waits only on its producer roles) ==========
        bool p2_on = (layer == 0) ? (s < T_) : (s >= 1);
        if (p2_on) {
            // ---- wait-independent loads issued BEFORE the wait (latency overlap)
            float2 bir = *reinterpret_cast<const float2*>(&bi[j0]);
            float2 bii = *reinterpret_cast<const float2*>(&bi[512 + j0]);
            float2 bin = *reinterpret_cast<const float2*>(&bi[1024 + j0]);
            float2 bhr = *reinterpret_cast<const float2*>(&bh[j0]);
            float2 bhi = *reinterpret_cast<const float2*>(&bh[512 + j0]);
            float2 bhn = *reinterpret_cast<const float2*>(&bh[1024 + j0]);
            float2 lgr = *reinterpret_cast<const float2*>(&lg[j0]);
            float2 lbr = *reinterpret_cast<const float2*>(&lb[j0]);
            float2 lgi = *reinterpret_cast<const float2*>(&lg[512 + j0]);
            float2 lbi = *reinterpret_cast<const float2*>(&lb[512 + j0]);
            float2 lgn = *reinterpret_cast<const float2*>(&lg[1024 + j0]);
            float2 lbn = *reinterpret_cast<const float2*>(&lb[1024 + j0]);
            float* hcur = layer ? g_h1 : g_h0;
            float2 hold = *reinterpret_cast<const float2*>(&hcur[b2i * 512 + j0]);

            if (layer == 0) waitset(g_cg, 0, 96, s + 1);
            else            waitset(g_cg, 32, 64, s + 1);

            const int t = (layer == 0) ? s : (s - 1);
            const float* gh = (layer ? g_gh1 : g_gh0) + (size_t)b2i * G3;
            const float* gi = (layer ? g_gi1[par] : g_gi0[par]) + (size_t)b2i * G3;

            float2 ghr = __ldcg(reinterpret_cast<const float2*>(&gh[j0]));
            float2 ghi = __ldcg(reinterpret_cast<const float2*>(&gh[512 + j0]));
            float2 ghn = __ldcg(reinterpret_cast<const float2*>(&gh[1024 + j0]));
            float2 gir = __ldcg(reinterpret_cast<const float2*>(&gi[j0]));
            float2 gii = __ldcg(reinterpret_cast<const float2*>(&gi[512 + j0]));
            float2 gin = __ldcg(reinterpret_cast<const float2*>(&gi[1024 + j0]));

            float2 A  = make_float2(gir.x + bir.x + ghr.x + bhr.x,
                                    gir.y + bir.y + ghr.y + bhr.y);
            float2 Bv = make_float2(gii.x + bii.x + ghi.x + bhi.x,
                                    gii.y + bii.y + ghi.y + bhi.y);
            float2 Ch = make_float2(ghn.x + bhn.x, ghn.y + bhn.y);
            float2 Dn = make_float2(gin.x + bin.x, gin.y + bin.y);

            float sr = A.x + A.y,   qr = A.x * A.x + A.y * A.y;
            float si = Bv.x + Bv.y, qi = Bv.x * Bv.x + Bv.y * Bv.y;
            blockReduce4(sr, qr, si, qi, red);

            const float inv = 1.0f / 512.0f;
            float mur = sr * inv, rr = rsqrtf(qr * inv - mur * mur + 1e-5f);
            float mui = si * inv, ri = rsqrtf(qi * inv - mui * mui + 1e-5f);

            float rgx = 1.0f / (1.0f + __expf(-((A.x - mur) * rr * lgr.x + lbr.x)));
            float rgy = 1.0f / (1.0f + __expf(-((A.y - mur) * rr * lgr.y + lbr.y)));
            float igx = 1.0f / (1.0f + __expf(-((Bv.x - mui) * ri * lgi.x + lbi.x)));
            float igy = 1.0f / (1.0f + __expf(-((Bv.y - mui) * ri * lgi.y + lbi.y)));

            float2 Cn = make_float2(Dn.x + rgx * Ch.x, Dn.y + rgy * Ch.y);

            float sn = Cn.x + Cn.y, qn = Cn.x * Cn.x + Cn.y * Cn.y;
            blockReduce2s(sn, qn, red);
            float mun = sn * inv, rn = rsqrtf(qn * inv - mun * mun + 1e-5f);

            float ngx = tanhf((Cn.x - mun) * rn * lgn.x + lbn.x);
            float ngy = tanhf((Cn.y - mun) * rn * lgn.y + lbn.y);

            float2 hy = make_float2(ngx + igx * (hold.x - ngx),
                                    ngy + igy * (hold.y - ngy));
            *reinterpret_cast<float2*>(&hcur[b2i * 512 + j0]) = hy;

            // packed hi/lo emission (same decomposition the stagers used before)
            uint32_t phi = pack_bf16(hy.x, hy.y);
            uint32_t plo = pack_bf16(hy.x - bf_lo(phi), hy.y - bf_hi(phi));
            uint2 pk = make_uint2(phi, plo);
            if (layer == 0) {
                g_h0p[b2i * 256 + tid] = pk;
                g_y0p[((size_t)t * B_ + b2i) * 256 + tid] = pk;
                if (t == T_ - 1)
                    *reinterpret_cast<float2*>(&hl0[b2i * 512 + j0]) = hy;
            } else {
                g_h1p[b2i * 256 + tid] = pk;
                *reinterpret_cast<float2*>(&out[((size_t)t * B_ + b2i) * H_ + j0]) = hy;
                if (t == T_ - 1)
                    *reinterpret_cast<float2*>(&hl1[b2i * 512 + j0]) = hy;
            }
        }

        signal(g_cp, (unsigned)(s + 1));
    }
}

// ---------------- launcher ----------------
extern "C" void kernel_launch(void* const* d_in, const int* in_sizes, int n_in,
                              void* d_out, int out_size) {
    (void)in_sizes; (void)n_in;
    const float* x   = (const float*)d_in[0];
    const float* h0  = (const float*)d_in[1];
    const float* Wih = (const float*)d_in[2];
    const float* bih = (const float*)d_in[3];
    const float* Whh = (const float*)d_in[4];
    const float* bhh = (const float*)d_in[5];
    const float* lng = (const float*)d_in[6];
    const float* lnb = (const float*)d_in[7];
    float* out = (float*)d_out;

    const size_t TBH = (size_t)T_ * B_ * H_;
    const size_t LBH = (size_t)2 * B_ * H_;
    bool has_hl = ((size_t)out_size >= TBH + LBH);

    float* hl_dummy = nullptr;
    cudaGetSymbolAddress((void**)&hl_dummy, g_dummy);
    float* hl0 = has_hl ? out + TBH           : hl_dummy;
    float* hl1 = has_hl ? out + TBH + B_ * H_ : hl_dummy;

    cudaFuncSetAttribute(k_fused, cudaFuncAttributeMaxDynamicSharedMemorySize,
                         SM_FUSED);

    // prologue: pack x (T*B*H/2 = 8,388,608 uint2 entries)
    k_packx<<<32768, 256>>>(x);
    k_init<<<NCTA, 256>>>(h0);
    k_fused<<<NCTA, 256, SM_FUSED>>>(
        Whh, Whh + (size_t)G3 * H_,
        Wih, Wih + (size_t)G3 * H_,
        bih, bhh, lng, lnb, out, hl0, hl1);
}